// round 1
// baseline (speedup 1.0000x reference)
#include <cuda_runtime.h>
#include <math.h>

#define T_STEPS 1024
#define NBATCH  128
#define NU      512
#define DIN     128
#define EPSF    0.01f
#define SCAN_CTAS 128
#define NC      4           // columns of A (and of W) per CTA: 128*4 = 512

// ---------------- device scratch (no runtime allocation allowed) -------------
__device__ float g_z[(size_t)T_STEPS * NU * NBATCH];  // [t][j][b]  256 MB
__device__ float g_h[2 * NBATCH * NU];                // ping-pong h buffers
__device__ unsigned g_bar_count;
__device__ volatile unsigned g_bar_phase;

// ---------------- software grid barrier (128 co-resident CTAs) ---------------
__device__ __forceinline__ void grid_barrier() {
    __syncthreads();
    if (threadIdx.x == 0) {
        unsigned ph = g_bar_phase;
        __threadfence();
        if (atomicAdd(&g_bar_count, 1u) == SCAN_CTAS - 1u) {
            atomicExch(&g_bar_count, 0u);
            __threadfence();
            g_bar_phase = ph + 1u;
        } else {
            while (g_bar_phase == ph) { __nanosleep(64); }
        }
        __threadfence();
    }
    __syncthreads();
}

// ---------------- z precompute: z[t][j][b] = sum_k x[b,t,k]*Ew[k,j] + Eb[j] --
#define Z_SMEM (128*132*4 + 128*64*4)   // xs[128][132] + ew[128][64]

__global__ void __launch_bounds__(256) z_kernel(const float* __restrict__ x,
                                                const float* __restrict__ Ew,
                                                const float* __restrict__ Eb) {
    extern __shared__ float sm[];
    float* xs = sm;              // [128][132]  (padded pitch)
    float* ew = sm + 128 * 132;  // [128][64]
    const int t   = blockIdx.x;
    const int tid = threadIdx.x;

    // load x[:, t, :] into smem (coalesced float4)
    for (int idx = tid; idx < 128 * 32; idx += 256) {
        int b  = idx >> 5;
        int kq = idx & 31;
        float4 v = *(const float4*)(x + ((size_t)b * T_STEPS + t) * DIN + kq * 4);
        *(float4*)(xs + b * 132 + kq * 4) = v;
    }

    const int bg = tid >> 3;     // 0..31  -> b0 = bg*4
    const int jg = tid & 7;      // 0..7   -> j0 = jg*8 (within 64-col block)
    const int b0 = bg * 4;
    const int j0 = jg * 8;

    for (int jb = 0; jb < 8; jb++) {
        __syncthreads();
        // stage E_w[:, jb*64 .. jb*64+63]
        for (int idx = tid; idx < 128 * 16; idx += 256) {
            int k  = idx >> 4;
            int jq = idx & 15;
            *(float4*)(ew + k * 64 + jq * 4) =
                *(const float4*)(Ew + (size_t)k * NU + jb * 64 + jq * 4);
        }
        __syncthreads();

        float acc[4][8];
        #pragma unroll
        for (int r = 0; r < 4; r++)
            #pragma unroll
            for (int jj = 0; jj < 8; jj++) acc[r][jj] = 0.f;

        #pragma unroll 2
        for (int k = 0; k < 128; k += 4) {
            float4 xv[4];
            #pragma unroll
            for (int r = 0; r < 4; r++)
                xv[r] = *(const float4*)(xs + (b0 + r) * 132 + k);
            #pragma unroll
            for (int kk = 0; kk < 4; kk++) {
                float4 e0 = *(const float4*)(ew + (k + kk) * 64 + j0);
                float4 e1 = *(const float4*)(ew + (k + kk) * 64 + j0 + 4);
                float ev0 = e0.x, ev1 = e0.y, ev2 = e0.z, ev3 = e0.w;
                float ev4 = e1.x, ev5 = e1.y, ev6 = e1.z, ev7 = e1.w;
                #pragma unroll
                for (int r = 0; r < 4; r++) {
                    float xk = (kk == 0) ? xv[r].x : (kk == 1) ? xv[r].y
                             : (kk == 2) ? xv[r].z : xv[r].w;
                    acc[r][0] += xk * ev0;  acc[r][1] += xk * ev1;
                    acc[r][2] += xk * ev2;  acc[r][3] += xk * ev3;
                    acc[r][4] += xk * ev4;  acc[r][5] += xk * ev5;
                    acc[r][6] += xk * ev6;  acc[r][7] += xk * ev7;
                }
            }
        }

        #pragma unroll
        for (int jj = 0; jj < 8; jj++) {
            int j = jb * 64 + j0 + jj;
            float bias = Eb[j];
            float4 v = make_float4(acc[0][jj] + bias, acc[1][jj] + bias,
                                   acc[2][jj] + bias, acc[3][jj] + bias);
            *(float4*)(g_z + ((size_t)t * NU + j) * NBATCH + b0) = v;
        }
    }
}

// ---------------- persistent scan kernel -------------------------------------
// smem: sW[8][512] (4 A-cols then 4 W-cols, K-major) + red[1024][8] = 48 KB
#define SCAN_SMEM (8 * 512 * 4 + 1024 * 8 * 4)

__global__ void __launch_bounds__(256) scan_kernel(const float* __restrict__ Bm,
                                                   const float* __restrict__ Cm,
                                                   const float* __restrict__ Dw,
                                                   const float* __restrict__ Db,
                                                   float* __restrict__ out) {
    extern __shared__ float sm[];
    float* sW  = sm;             // [8][512]
    float* red = sm + 8 * 512;   // [1024][8]
    const int cta  = blockIdx.x;   // 0..127
    const int tid  = threadIdx.x;
    const int col0 = cta * NC;

    // Build this CTA's 4 columns of A and W:
    //   A[k][j] = B[k][j] - 0.6*B[j][k] - 0.01*(k==j)   (BETA=0.8 folded)
    for (int idx = tid; idx < NC * 512; idx += 256) {
        int jj = idx >> 9;
        int k  = idx & 511;
        int j  = col0 + jj;
        float diag = (k == j) ? 0.01f : 0.0f;
        sW[jj * 512 + k]       = Bm[(size_t)k * NU + j] - 0.6f * Bm[(size_t)j * NU + k] - diag;
        sW[(4 + jj) * 512 + k] = Cm[(size_t)k * NU + j] - 0.6f * Cm[(size_t)j * NU + k] - diag;
    }
    // zero h0 (this CTA's columns)
    for (int idx = tid; idx < NBATCH * NC; idx += 256) {
        int b = idx >> 2; int jj = idx & 3;
        g_h[b * NU + col0 + jj] = 0.f;
    }
    grid_barrier();

    const int ks = tid & 7;    // k-split 0..7 (interleaved 16B chunks)
    const int bg = tid >> 3;   // 0..31
    const int b0 = bg * 4;
    float* hcur = g_h;
    float* hnxt = g_h + NBATCH * NU;

    for (int t = 0; t < T_STEPS; t++) {
        float accA[4][4], accW[4][4];
        #pragma unroll
        for (int r = 0; r < 4; r++)
            #pragma unroll
            for (int jj = 0; jj < 4; jj++) { accA[r][jj] = 0.f; accW[r][jj] = 0.f; }

        #pragma unroll 4
        for (int i = 0; i < 16; i++) {
            int k = i * 32 + ks * 4;
            float4 hv[4];
            #pragma unroll
            for (int r = 0; r < 4; r++)   // L2-only load: h written by other CTAs
                hv[r] = __ldcg((const float4*)(hcur + (b0 + r) * NU + k));
            #pragma unroll
            for (int jj = 0; jj < 4; jj++) {
                float4 av = *(const float4*)(sW + jj * 512 + k);
                float4 wv = *(const float4*)(sW + (4 + jj) * 512 + k);
                #pragma unroll
                for (int r = 0; r < 4; r++) {
                    accA[r][jj] += hv[r].x * av.x + hv[r].y * av.y
                                 + hv[r].z * av.z + hv[r].w * av.w;
                    accW[r][jj] += hv[r].x * wv.x + hv[r].y * wv.y
                                 + hv[r].z * wv.z + hv[r].w * wv.w;
                }
            }
        }

        // stage k-split partials: red[o][ks], o = ((b*4+jj)*2 + {A:0,W:1})
        #pragma unroll
        for (int r = 0; r < 4; r++)
            #pragma unroll
            for (int jj = 0; jj < 4; jj++) {
                int o = (((b0 + r) * NC + jj) << 1);
                red[o * 8 + ks]       = accA[r][jj];
                red[(o + 1) * 8 + ks] = accW[r][jj];
            }
        __syncthreads();

        // reduce + pointwise update; each thread finishes 2 (b, col) pairs
        #pragma unroll
        for (int q = 0; q < 2; q++) {
            int p  = tid * 2 + q;      // 0..511
            int b  = p >> 2;
            int jj = p & 3;
            int oA = ((b * NC + jj) << 1);
            float da = 0.f, dw = 0.f;
            #pragma unroll
            for (int s = 0; s < 8; s++) {
                da += red[oA * 8 + s];
                dw += red[(oA + 1) * 8 + s];
            }
            float zv   = g_z[((size_t)t * NU + col0 + jj) * NBATCH + b];
            float hold = __ldcg(hcur + b * NU + col0 + jj);
            float hnew = hold + EPSF * da + EPSF * tanhf(dw + zv);
            hnxt[b * NU + col0 + jj] = hnew;
        }
        grid_barrier();
        float* tmp = hcur; hcur = hnxt; hnxt = tmp;
    }

    // ------------- epilogue: out[b][c] = h_final[b] . Dw[:,c] + Db[c] --------
    {
        int b = cta;                       // 128 CTAs == 128 batch rows
        float part[10];
        #pragma unroll
        for (int c = 0; c < 10; c++) part[c] = 0.f;
        for (int k = tid; k < NU; k += 256) {
            float hv = __ldcg(hcur + b * NU + k);
            #pragma unroll
            for (int c = 0; c < 10; c++) part[c] += hv * Dw[k * 10 + c];
        }
        __syncthreads();
        #pragma unroll
        for (int c = 0; c < 10; c++) red[c * 256 + tid] = part[c];
        __syncthreads();
        if (tid < 10) {
            float s = Db[tid];
            for (int i = 0; i < 256; i++) s += red[tid * 256 + i];
            out[b * 10 + tid] = s;
        }
    }
}

// ---------------- launch ------------------------------------------------------
extern "C" void kernel_launch(void* const* d_in, const int* in_sizes, int n_in,
                              void* d_out, int out_size) {
    const float* x  = (const float*)d_in[0];
    const float* B  = (const float*)d_in[1];
    const float* C  = (const float*)d_in[2];
    const float* Ew = (const float*)d_in[3];
    const float* Eb = (const float*)d_in[4];
    const float* Dw = (const float*)d_in[5];
    const float* Db = (const float*)d_in[6];
    float* out = (float*)d_out;

    cudaFuncSetAttribute(z_kernel, cudaFuncAttributeMaxDynamicSharedMemorySize, Z_SMEM);
    cudaFuncSetAttribute(scan_kernel, cudaFuncAttributeMaxDynamicSharedMemorySize, SCAN_SMEM);

    z_kernel<<<T_STEPS, 256, Z_SMEM>>>(x, Ew, Eb);
    scan_kernel<<<SCAN_CTAS, 256, SCAN_SMEM>>>(B, C, Dw, Db, out);
}

// round 2
// speedup vs baseline: 1.1484x; 1.1484x over previous
#include <cuda_runtime.h>
#include <math.h>

#define T_STEPS 1024
#define NBATCH  128
#define NU      512
#define DIN     128
#define EPSF    0.01f
#define SCAN_CTAS 128
#define HSZ     (NBATCH * NU)
#define SCAN_SMEM ((64 * 512 + 16 * 512) * 4)   // weights[64][512] + h-tile[16][512] = 160KB
#define Z_SMEM (128 * 132 * 4 + 128 * 64 * 4)

// ---------------- device scratch --------------------------------------------
__device__ float g_z[(size_t)T_STEPS * NU * NBATCH];  // [t][j][b]
__device__ float g_h[2 * HSZ];                        // ping-pong h
__device__ unsigned g_bar_count;
__device__ volatile unsigned g_bar_phase;

// ---------------- fallback grid barrier --------------------------------------
__device__ __forceinline__ void grid_barrier() {
    __syncthreads();
    if (threadIdx.x == 0) {
        unsigned ph = g_bar_phase;
        __threadfence();
        if (atomicAdd(&g_bar_count, 1u) == SCAN_CTAS - 1u) {
            atomicExch(&g_bar_count, 0u);
            __threadfence();
            g_bar_phase = ph + 1u;
        } else {
            while (g_bar_phase == ph) { __nanosleep(32); }
        }
        __threadfence();
    }
    __syncthreads();
}

// ---------------- z precompute: z[t][j][b] -----------------------------------
__global__ void __launch_bounds__(256) z_kernel(const float* __restrict__ x,
                                                const float* __restrict__ Ew,
                                                const float* __restrict__ Eb) {
    extern __shared__ float sm[];
    float* xs = sm;              // [128][132]
    float* ew = sm + 128 * 132;  // [128][64]
    const int t   = blockIdx.x;
    const int tid = threadIdx.x;

    for (int idx = tid; idx < 128 * 32; idx += 256) {
        int b  = idx >> 5;
        int kq = idx & 31;
        float4 v = *(const float4*)(x + ((size_t)b * T_STEPS + t) * DIN + kq * 4);
        *(float4*)(xs + b * 132 + kq * 4) = v;
    }

    const int bg = tid >> 3;
    const int jg = tid & 7;
    const int b0 = bg * 4;
    const int j0 = jg * 8;

    for (int jb = 0; jb < 8; jb++) {
        __syncthreads();
        for (int idx = tid; idx < 128 * 16; idx += 256) {
            int k  = idx >> 4;
            int jq = idx & 15;
            *(float4*)(ew + k * 64 + jq * 4) =
                *(const float4*)(Ew + (size_t)k * NU + jb * 64 + jq * 4);
        }
        __syncthreads();

        float acc[4][8];
        #pragma unroll
        for (int r = 0; r < 4; r++)
            #pragma unroll
            for (int jj = 0; jj < 8; jj++) acc[r][jj] = 0.f;

        #pragma unroll 2
        for (int k = 0; k < 128; k += 4) {
            float4 xv[4];
            #pragma unroll
            for (int r = 0; r < 4; r++)
                xv[r] = *(const float4*)(xs + (b0 + r) * 132 + k);
            #pragma unroll
            for (int kk = 0; kk < 4; kk++) {
                float4 e0 = *(const float4*)(ew + (k + kk) * 64 + j0);
                float4 e1 = *(const float4*)(ew + (k + kk) * 64 + j0 + 4);
                #pragma unroll
                for (int r = 0; r < 4; r++) {
                    float xk = (kk == 0) ? xv[r].x : (kk == 1) ? xv[r].y
                             : (kk == 2) ? xv[r].z : xv[r].w;
                    acc[r][0] += xk * e0.x;  acc[r][1] += xk * e0.y;
                    acc[r][2] += xk * e0.z;  acc[r][3] += xk * e0.w;
                    acc[r][4] += xk * e1.x;  acc[r][5] += xk * e1.y;
                    acc[r][6] += xk * e1.z;  acc[r][7] += xk * e1.w;
                }
            }
        }

        #pragma unroll
        for (int jj = 0; jj < 8; jj++) {
            int j = jb * 64 + j0 + jj;
            float bias = Eb[j];
            float4 v = make_float4(acc[0][jj] + bias, acc[1][jj] + bias,
                                   acc[2][jj] + bias, acc[3][jj] + bias);
            *(float4*)(g_z + ((size_t)t * NU + j) * NBATCH + b0) = v;
        }
    }
}

// ---------------- scan kernel: 8 clusters x 16 CTAs --------------------------
// CTA (bb = cta>>4, rk = cta&15): batch rows [bb*16, bb*16+16), cols [rk*32, rk*32+32)
// smem: sW[64][512] (32 A'-cols (EPS folded) + 32 W-cols, K-major), sh[16][512] h tile
template <bool CLU>
__global__ void __launch_bounds__(256) scan_kernel(const float* __restrict__ Bm,
                                                   const float* __restrict__ Cm,
                                                   const float* __restrict__ Dw,
                                                   const float* __restrict__ Db,
                                                   float* __restrict__ out) {
    extern __shared__ float sm[];
    float* sW = sm;              // [64][512]
    float* sh = sm + 64 * 512;   // [16][512]
    const int cta  = blockIdx.x;
    const int bb   = cta >> 4;
    const int col0 = (cta & 15) * 32;
    const int tid  = threadIdx.x;

    // build weights: A'[k][j] = EPS*(B[k][j] - 0.6*B[j][k] - 0.01 d), W plain
    for (int idx = tid; idx < 32 * 512; idx += 256) {
        int jj = idx >> 9;
        int k  = idx & 511;
        int j  = col0 + jj;
        float d = (k == j) ? 0.01f : 0.0f;
        sW[jj * 512 + k]        = EPSF * (Bm[(size_t)k * NU + j] - 0.6f * Bm[(size_t)j * NU + k] - d);
        sW[(32 + jj) * 512 + k] = Cm[(size_t)k * NU + j] - 0.6f * Cm[(size_t)j * NU + k] - d;
    }
    for (int idx = tid; idx < 16 * 512; idx += 256) sh[idx] = 0.f;   // h0 = 0
    __syncthreads();

    // thread layout: warp w (j-group, 4 cols), quad q (b-group, 4 rows), ks (k-split 8)
    const int ks = tid & 7;
    const int q  = (tid >> 3) & 3;
    const int w  = tid >> 5;
    const float* hb = sh + q * 4 * 512;
    const float* wA = sW + (w * 4) * 512;
    const float* wW = sW + (32 + w * 4) * 512;

    // pointwise assignment: lane ks handles pairs (r = ks>>1, jj0 = (ks&1)*2, jj0+1)
    const int p0  = ks * 2;
    const int r_p = ks >> 1;
    const int bl  = q * 4 + r_p;
    const int jl0 = w * 4 + (ks & 1) * 2;
    const int jg0 = col0 + jl0;           // even -> float2-aligned writes
    const int bg  = bb * 16 + bl;

    for (int t = 0; t < T_STEPS; t++) {
        float accA[4][4], accW[4][4];
        #pragma unroll
        for (int r = 0; r < 4; r++)
            #pragma unroll
            for (int jj = 0; jj < 4; jj++) { accA[r][jj] = 0.f; accW[r][jj] = 0.f; }

        #pragma unroll 2
        for (int i = 0; i < 16; i++) {
            const int k = i * 32 + ks * 4;
            float4 hv0 = *(const float4*)(hb + 0 * 512 + k);
            float4 hv1 = *(const float4*)(hb + 1 * 512 + k);
            float4 hv2 = *(const float4*)(hb + 2 * 512 + k);
            float4 hv3 = *(const float4*)(hb + 3 * 512 + k);
            #pragma unroll
            for (int jj = 0; jj < 4; jj++) {
                float4 av = *(const float4*)(wA + jj * 512 + k);
                float4 wv = *(const float4*)(wW + jj * 512 + k);
                accA[0][jj] += hv0.x * av.x + hv0.y * av.y + hv0.z * av.z + hv0.w * av.w;
                accA[1][jj] += hv1.x * av.x + hv1.y * av.y + hv1.z * av.z + hv1.w * av.w;
                accA[2][jj] += hv2.x * av.x + hv2.y * av.y + hv2.z * av.z + hv2.w * av.w;
                accA[3][jj] += hv3.x * av.x + hv3.y * av.y + hv3.z * av.z + hv3.w * av.w;
                accW[0][jj] += hv0.x * wv.x + hv0.y * wv.y + hv0.z * wv.z + hv0.w * wv.w;
                accW[1][jj] += hv1.x * wv.x + hv1.y * wv.y + hv1.z * wv.z + hv1.w * wv.w;
                accW[2][jj] += hv2.x * wv.x + hv2.y * wv.y + hv2.z * wv.z + hv2.w * wv.w;
                accW[3][jj] += hv3.x * wv.x + hv3.y * wv.y + hv3.z * wv.z + hv3.w * wv.w;
            }
        }

        // issue z loads early (L2 latency hides behind reduction)
        float zv0 = __ldcg(g_z + ((size_t)t * NU + jg0) * NBATCH + bg);
        float zv1 = __ldcg(g_z + ((size_t)t * NU + jg0 + 1) * NBATCH + bg);

        // xor-shuffle reduction across the 8 ks lanes of each quad
        #pragma unroll
        for (int r = 0; r < 4; r++)
            #pragma unroll
            for (int jj = 0; jj < 4; jj++) {
                #pragma unroll
                for (int m = 1; m < 8; m <<= 1) {
                    accA[r][jj] += __shfl_xor_sync(0xffffffffu, accA[r][jj], m);
                    accW[r][jj] += __shfl_xor_sync(0xffffffffu, accW[r][jj], m);
                }
            }

        // static-index extraction of this lane's two pairs (predicated selects)
        float da0 = 0.f, dw0 = 0.f, da1 = 0.f, dw1 = 0.f;
        #pragma unroll
        for (int r = 0; r < 4; r++)
            #pragma unroll
            for (int j2 = 0; j2 < 2; j2++) {
                if (r * 4 + j2 * 2 == p0) {
                    da0 = accA[r][j2 * 2];     dw0 = accW[r][j2 * 2];
                    da1 = accA[r][j2 * 2 + 1]; dw1 = accW[r][j2 * 2 + 1];
                }
            }

        float h0 = sh[bl * 512 + jg0];
        float h1 = sh[bl * 512 + jg0 + 1];
        float hn0 = h0 + da0 + EPSF * tanhf(dw0 + zv0);
        float hn1 = h1 + da1 + EPSF * tanhf(dw1 + zv1);
        float* dst = g_h + (size_t)(t & 1) * HSZ;
        *(float2*)(dst + (size_t)bg * 512 + jg0) = make_float2(hn0, hn1);

        if (CLU) {
            asm volatile("barrier.cluster.arrive.aligned;" ::: "memory");
            asm volatile("barrier.cluster.wait.aligned;" ::: "memory");
        } else {
            grid_barrier();
        }

        if (t < T_STEPS - 1) {
            const float4* src = (const float4*)(g_h + (size_t)(t & 1) * HSZ + (size_t)bb * 16 * 512);
            float4* d4 = (float4*)sh;
            #pragma unroll
            for (int c = 0; c < 8; c++)
                d4[c * 256 + tid] = __ldcg(src + c * 256 + tid);
            __syncthreads();
        }
    }

    // ---------------- epilogue: out[b] = h_final[b] @ Dw + Db ----------------
    {
        const int b = cta;   // bb*16 + rank == cta; row written by this cluster
        const float* hf = g_h + HSZ + (size_t)b * 512;   // (T-1)&1 == 1
        float part[10];
        #pragma unroll
        for (int c = 0; c < 10; c++) part[c] = 0.f;
        for (int k = tid; k < NU; k += 256) {
            float hv = __ldcg(hf + k);
            #pragma unroll
            for (int c = 0; c < 10; c++) part[c] += hv * Dw[k * 10 + c];
        }
        __syncthreads();   // done with sW, reuse as reduction buffer
        #pragma unroll
        for (int c = 0; c < 10; c++) sm[c * 256 + tid] = part[c];
        __syncthreads();
        if (tid < 10) {
            float s = Db[tid];
            for (int i = 0; i < 256; i++) s += sm[tid * 256 + i];
            out[b * 10 + tid] = s;
        }
    }
}

// ---------------- launch ------------------------------------------------------
extern "C" void kernel_launch(void* const* d_in, const int* in_sizes, int n_in,
                              void* d_out, int out_size) {
    const float* x  = (const float*)d_in[0];
    const float* B  = (const float*)d_in[1];
    const float* C  = (const float*)d_in[2];
    const float* Ew = (const float*)d_in[3];
    const float* Eb = (const float*)d_in[4];
    const float* Dw = (const float*)d_in[5];
    const float* Db = (const float*)d_in[6];
    float* outp = (float*)d_out;

    cudaFuncSetAttribute(z_kernel, cudaFuncAttributeMaxDynamicSharedMemorySize, Z_SMEM);
    cudaFuncSetAttribute(scan_kernel<true>, cudaFuncAttributeMaxDynamicSharedMemorySize, SCAN_SMEM);
    cudaFuncSetAttribute(scan_kernel<true>, cudaFuncAttributeNonPortableClusterSizeAllowed, 1);
    cudaFuncSetAttribute(scan_kernel<false>, cudaFuncAttributeMaxDynamicSharedMemorySize, SCAN_SMEM);

    z_kernel<<<T_STEPS, 256, Z_SMEM>>>(x, Ew, Eb);

    cudaLaunchConfig_t cfg = {};
    cfg.gridDim  = dim3(SCAN_CTAS, 1, 1);
    cfg.blockDim = dim3(256, 1, 1);
    cfg.dynamicSmemBytes = SCAN_SMEM;
    cfg.stream = 0;
    cudaLaunchAttribute at[1];
    at[0].id = cudaLaunchAttributeClusterDimension;
    at[0].val.clusterDim.x = 16;
    at[0].val.clusterDim.y = 1;
    at[0].val.clusterDim.z = 1;
    cfg.attrs = at;
    cfg.numAttrs = 1;

    int ncl = 0;
    cudaError_t qe = cudaOccupancyMaxActiveClusters(&ncl, scan_kernel<true>, &cfg);
    if (qe == cudaSuccess && ncl >= 1) {
        // clusters are mutually independent (batch rows independent) -> safe
        cudaLaunchKernelEx(&cfg, scan_kernel<true>, B, C, Dw, Db, outp);
    } else {
        cudaGetLastError();  // clear
        scan_kernel<false><<<SCAN_CTAS, 256, SCAN_SMEM>>>(B, C, Dw, Db, outp);
    }
}